// round 13
// baseline (speedup 1.0000x reference)
#include <cuda_runtime.h>

// YOLO postprocess: filter(score>0.5) -> sort desc -> greedy NMS(IoU>0.5) -> masked rows.
// x: (1, 84, 8400) f32 channel-major; out: (8400, 5) f32.
//
//   K0 filter (warp-aggregated compaction)
//   K1 rank-by-counting sort + gather (4 threads/key, smem tiles)
//   K2 sparse suppression edge list (64x64 tiles, 4 threads/row, triangle grid)
//   K3 exact greedy fixed-point: block rounds while live-edge set is large,
//      single-warp rounds once it compacts small; fused output; self-reset
//
// Greedy NMS == unique fixed point of:
//   j SUP  iff exists edge (i,j), i<j, i KEEP
//   j KEEP iff every edge (i,j) has i SUP
// Each round the minimum-index unknown row settles => guaranteed convergence.

#define N_IN   8400
#define NSORT  8192
#define FULLW  0xffffffffu
#define ECAP   (1 << 20)      // edge capacity (4 MB scratch; ~25k expected)
#define EBUF   24576          // edges per ping-pong smem buffer (96 KB each)
#define NB32   256            // 8192 bits / 32
#define WTHRESH 2048          // switch to warp mode below this live count

// ---------------- global scratch ----------------
__device__ int    g_cnt;      // zero at rest (reset by K3)
__device__ int    g_ecnt;     // zero at rest (reset by K3)
__device__ unsigned long long g_keys[NSORT];
__device__ __align__(16) float4 g_boxes[NSORT];
__device__ float  g_score[NSORT];
__device__ float  g_area[NSORT];
__device__ unsigned g_edges[ECAP];

// ---------------- K0: filter + compact (order canonicalized by K1) --------
extern "C" __global__ void __launch_bounds__(256)
k0_filter_kernel(const float* __restrict__ x)
{
    const int n = blockIdx.x * 256 + threadIdx.x;
    bool pass = false;
    float s = 0.f;
    if (n < N_IN) {
        s = x[4 * N_IN + n];
        pass = (s > 0.5f);
    }
    unsigned m = __ballot_sync(FULLW, pass);
    if (!m) return;
    int lane = threadIdx.x & 31;
    int leader = __ffs(m) - 1;
    int base = 0;
    if (lane == leader) base = atomicAdd(&g_cnt, __popc(m));
    base = __shfl_sync(FULLW, base, leader);
    if (pass) {
        int slot = base + __popc(m & ((1u << lane) - 1));
        if (slot < NSORT) {
            unsigned sb = __float_as_uint(s);
            g_keys[slot] = ((unsigned long long)(~sb) << 32) | (unsigned)n;
        }
    }
}

// ---------------- K1: rank-by-counting sort + gather (4 threads/key) ------
// keys unique (idx in low bits) => rank is an exact permutation.
// key = (~score_bits)<<32 | idx : ascending == descending score, stable ties.
extern "C" __global__ void __launch_bounds__(256)
k1_rank_kernel(const float* __restrict__ x)
{
    __shared__ unsigned long long tile[256];
    __shared__ int srank[64][4];
    const int M = min(g_cnt, NSORT);
    if ((int)(blockIdx.x * 64) >= M) return;          // uniform block early-exit

    const int tid   = threadIdx.x;
    const int key_l = tid & 63;
    const int sub   = tid >> 6;
    const int kslot = blockIdx.x * 64 + key_l;
    const unsigned long long mykey = (kslot < M) ? g_keys[kslot] : ~0ULL;

    int cnt = 0;
    for (int base = 0; base < M; base += 256) {
        int c = base + tid;
        tile[tid] = (c < M) ? g_keys[c] : ~0ULL;      // sentinel never counts
        __syncthreads();
        const unsigned long long* tp = tile + (sub << 6);   // warp-broadcast reads
#pragma unroll 16
        for (int j = 0; j < 64; j++)
            cnt += (tp[j] < mykey);
        __syncthreads();
    }
    srank[key_l][sub] = cnt;
    __syncthreads();

    if (sub == 0 && kslot < M) {
        int rank = srank[key_l][0] + srank[key_l][1]
                 + srank[key_l][2] + srank[key_l][3];
        int idx = (int)(unsigned)mykey;
        float X1 = x[idx];
        float Y1 = x[N_IN + idx];
        float X2 = x[2 * N_IN + idx];
        float Y2 = x[3 * N_IN + idx];
        g_boxes[rank] = make_float4(X1, Y1, X2, Y2);
        g_score[rank] = __uint_as_float(~(unsigned)(mykey >> 32));
        g_area[rank]  = (X2 - X1) * (Y2 - Y1);
    }
}

// ---------------- K2: sparse edges (64x64 tiles, 4 threads/row) -----------
// Triangle-linear grid (ty <= tx); edge (i,j), i<j, packed (i<<13)|j when
//   IoU > 0.5 <=> 3*inter > area_i + area_j + 1e-9 (denominator always > 0).
#define NCT64   (NSORT / 64)                     // 128
#define K2_GRID (NCT64 * (NCT64 + 1) / 2)        // 8256

extern "C" __global__ void __launch_bounds__(256)
k2_edges_kernel()
{
    // linear -> (ty <= tx) triangle decode
    const int L = blockIdx.x;
    int tx = (int)((sqrtf(8.0f * (float)L + 1.0f) - 1.0f) * 0.5f);
    while ((tx + 1) * (tx + 2) / 2 <= L) tx++;
    while (tx * (tx + 1) / 2 > L) tx--;
    const int ty = L - tx * (tx + 1) / 2;

    const int M = min(g_cnt, NSORT);
    const int nct = (M + 63) >> 6;
    if (ty >= nct || tx >= nct) return;

    __shared__ float4 cb[64];
    __shared__ float  ca[64];
    __shared__ unsigned ebuf[4096];     // worst case: full 64x64 tile
    __shared__ int ec, gbase;
    const int t  = threadIdx.x;
    if (t == 0) ec = 0;
    const int j0 = tx << 6;
    if (t < 64) {
        int jg = j0 + t;
        if (jg < M) { cb[t] = g_boxes[jg]; ca[t] = g_area[jg]; }
        else        { cb[t] = make_float4(0, 0, 0, 0); ca[t] = 1e30f; }
    }
    __syncthreads();

    const int row = t >> 2, sub = t & 3;
    const int i   = (ty << 6) + row;
    if (i < M) {
        const float4 b  = g_boxes[i];
        const float  sA = g_area[i] + 1e-9f;
        const int    c1 = min((sub << 4) + 16, M - j0);
#pragma unroll 4
        for (int c = sub << 4; c < c1; c++) {
            int j = j0 + c;
            if (j > i) {
                float4 q = cb[c];
                float iw = fminf(b.z, q.z) - fmaxf(b.x, q.x);
                float ih = fminf(b.w, q.w) - fmaxf(b.y, q.y);
                float inter = fmaxf(iw, 0.f) * fmaxf(ih, 0.f);
                if (3.0f * inter > sA + ca[c]) {
                    int p = atomicAdd(&ec, 1);
                    ebuf[p] = ((unsigned)i << 13) | (unsigned)j;
                }
            }
        }
    }
    __syncthreads();
    if (t == 0 && ec > 0) gbase = atomicAdd(&g_ecnt, ec);
    __syncthreads();
    for (int p = t; p < ec; p += 256) {
        int gp = gbase + p;
        if (gp < ECAP) g_edges[gp] = ebuf[p];
    }
}

// ---------------- K3: two-mode fixed point + fused output -----------------
#define K3_SMEM (2 * EBUF * 4)     // 192 KB ping-pong edge buffers

extern "C" __global__ void __launch_bounds__(1024, 1)
k3_fixed_kernel(float* __restrict__ out)
{
    extern __shared__ unsigned se[];                  // [2][EBUF]
    __shared__ unsigned keepb[NB32], supb[NB32], nsup[NB32], unkp[NB32];
    __shared__ int notdone, livecnt;
    const int M   = min(g_cnt, NSORT);
    const int tid = threadIdx.x, lane = tid & 31;
    int E = g_ecnt; if (E > ECAP) E = ECAP;
    const int Eover = (E > EBUF) ? (E - EBUF) : 0;    // stays in global, uncompacted

    unsigned* cur = se;
    unsigned* nxt = se + EBUF;
    int curN = min(E, EBUF);

    for (int e = tid; e < curN; e += 1024) cur[e] = g_edges[e];
    if (tid < NB32) { keepb[tid] = 0u; supb[tid] = 0u; }
    __syncthreads();

    // classify an edge; returns live (both endpoints unknown)
    auto classify = [&](unsigned ed) -> bool {
        int i = (int)(ed >> 13), j = (int)(ed & 8191u);
        unsigned jset = (keepb[j >> 5] | supb[j >> 5]) >> (j & 31);
        if (jset & 1u) return false;                      // j settled
        if ((keepb[i >> 5] >> (i & 31)) & 1u) {
            atomicOr(&nsup[j >> 5], 1u << (j & 31));      // KEEP pred -> SUP
            return false;
        }
        if ((supb[i >> 5] >> (i & 31)) & 1u) return false; // vacuous edge
        atomicOr(&unkp[j >> 5], 1u << (j & 31));          // UNKNOWN pred
        return true;
    };
    auto validw = [&](int w) -> unsigned {
        int base = w << 5;
        return (base + 32 <= M) ? 0xffffffffu
             : (base >= M ? 0u : ((1u << (M - base)) - 1u));
    };

    // ---- block-mode rounds (large live set) ----
    bool warpmode = false;
    for (int round = 0; round < NSORT; round++) {
        if (tid < NB32) { nsup[tid] = 0u; unkp[tid] = 0u; }
        if (tid == 0) { notdone = 0; livecnt = 0; }
        __syncthreads();

        for (int e0 = 0; e0 < curN; e0 += 1024) {
            int e = e0 + tid;
            bool act = (e < curN);
            unsigned ed = act ? cur[e] : 0u;
            bool live = act && classify(ed);
            unsigned m = __ballot_sync(FULLW, live);
            if (m) {
                int leader = __ffs(m) - 1;
                int base = 0;
                if (lane == leader) base = atomicAdd(&livecnt, __popc(m));
                base = __shfl_sync(FULLW, base, leader);
                if (live) nxt[base + __popc(m & ((1u << lane) - 1))] = ed;
            }
        }
        for (int e = tid; e < Eover; e += 1024) classify(g_edges[EBUF + e]);
        __syncthreads();

        if (tid < NB32) {
            unsigned valid = validw(tid);
            unsigned unk = ~(keepb[tid] | supb[tid]) & valid;
            if (unk) {
                unsigned ns = nsup[tid] & unk;
                unsigned nk = unk & ~nsup[tid] & ~unkp[tid];
                supb[tid]  |= ns;
                keepb[tid] |= nk;
                if (unk & ~(ns | nk)) notdone = 1;            // benign race
            }
        }
        __syncthreads();
        if (!notdone) break;
        curN = livecnt;
        unsigned* tmp = cur; cur = nxt; nxt = tmp;
        __syncthreads();     // livecnt read complete before next-round reset
        if (curN <= WTHRESH && Eover == 0) { warpmode = true; break; }
    }

    // ---- warp-mode rounds (small live set; warp 0 only, syncwarp) ----
    if (warpmode) {
        if (tid < 32) {
            for (;;) {
                for (int w = lane; w < NB32; w += 32) { nsup[w] = 0u; unkp[w] = 0u; }
                __syncwarp();

                int newcnt = 0;
                for (int e0 = 0; e0 < curN; e0 += 32) {
                    int e = e0 + lane;
                    bool act = (e < curN);
                    unsigned ed = act ? cur[e] : 0u;
                    bool live = act && classify(ed);
                    unsigned m = __ballot_sync(FULLW, live);
                    if (live) nxt[newcnt + __popc(m & ((1u << lane) - 1))] = ed;
                    newcnt += __popc(m);
                }
                __syncwarp();

                bool any = false;
                for (int w = lane; w < NB32; w += 32) {
                    unsigned valid = validw(w);
                    unsigned unk = ~(keepb[w] | supb[w]) & valid;
                    if (unk) {
                        unsigned ns = nsup[w] & unk;
                        unsigned nk = unk & ~nsup[w] & ~unkp[w];
                        supb[w]  |= ns;            // word owned by this lane
                        keepb[w] |= nk;
                        if (unk & ~(ns | nk)) any = true;
                    }
                }
                if (!__any_sync(FULLW, any)) break;
                curN = newcnt;
                unsigned* tmp = cur; cur = nxt; nxt = tmp;
                __syncwarp();
            }
        }
        __syncthreads();     // other warps wait here for warp 0
    }

    // ---- fused masked output write ----
    for (int r = tid; r < N_IN; r += 1024) {
        if (r < M) {
            float m = (float)((keepb[r >> 5] >> (r & 31)) & 1u);
            float4 b = g_boxes[r];
            out[r * 5 + 0] = b.x * m;
            out[r * 5 + 1] = b.y * m;
            out[r * 5 + 2] = b.z * m;
            out[r * 5 + 3] = b.w * m;
            out[r * 5 + 4] = g_score[r] * m;
        } else {
            out[r * 5 + 0] = 0.f;
            out[r * 5 + 1] = 0.f;
            out[r * 5 + 2] = 0.f;
            out[r * 5 + 3] = 0.f;
            out[r * 5 + 4] = 0.f;
        }
    }

    // restore zero-invariants for next call / graph replay
    if (tid == 0) { g_cnt = 0; g_ecnt = 0; }
}

// ---------------- launcher ----------------
extern "C" void kernel_launch(void* const* d_in, const int* in_sizes, int n_in,
                              void* d_out, int out_size)
{
    (void)in_sizes; (void)n_in; (void)out_size;
    const float* x = (const float*)d_in[0];
    float* out = (float*)d_out;

    static bool init_done = false;
    if (!init_done) {
        cudaFuncSetAttribute(k3_fixed_kernel,
                             cudaFuncAttributeMaxDynamicSharedMemorySize, K3_SMEM);
        init_done = true;
    }

    k0_filter_kernel<<<(N_IN + 255) / 256, 256>>>(x);
    k1_rank_kernel<<<NSORT / 64, 256>>>(x);
    k2_edges_kernel<<<K2_GRID, 256>>>();
    k3_fixed_kernel<<<1, 1024, K3_SMEM>>>(out);
}

// round 14
// speedup vs baseline: 1.0604x; 1.0604x over previous
#include <cuda_runtime.h>

// YOLO postprocess: filter(score>0.5) -> sort desc -> greedy NMS(IoU>0.5) -> masked rows.
// x: (1, 84, 8400) f32 channel-major; out: (8400, 5) f32.
//
//   K0 filter (warp-aggregated compaction)
//   K1 rank-by-counting sort + gather (4 threads/key, smem tiles)
//   K2 sparse suppression edge list (64x64 tiles, 4 threads/row, triangle grid)
//   K3 exact greedy fixed-point with live-edge ping-pong compaction,
//      fused masked output write, self-reset
//
// Greedy NMS == unique fixed point of:
//   j SUP  iff exists edge (i,j), i<j, i KEEP
//   j KEEP iff every edge (i,j) has i SUP
// Each round the minimum-index unknown row settles => guaranteed convergence.

#define N_IN   8400
#define NSORT  8192
#define FULLW  0xffffffffu
#define ECAP   (1 << 20)      // edge capacity (4 MB scratch; ~25k expected)
#define EBUF   24576          // edges per ping-pong smem buffer (96 KB each)
#define NB32   256            // 8192 bits / 32

// ---------------- global scratch ----------------
__device__ int    g_cnt;      // zero at rest (reset by K3)
__device__ int    g_ecnt;     // zero at rest (reset by K3)
__device__ unsigned long long g_keys[NSORT];
__device__ __align__(16) float4 g_boxes[NSORT];
__device__ float  g_score[NSORT];
__device__ float  g_area[NSORT];
__device__ unsigned g_edges[ECAP];

// ---------------- K0: filter + compact (order canonicalized by K1) --------
extern "C" __global__ void __launch_bounds__(256)
k0_filter_kernel(const float* __restrict__ x)
{
    const int n = blockIdx.x * 256 + threadIdx.x;
    bool pass = false;
    float s = 0.f;
    if (n < N_IN) {
        s = x[4 * N_IN + n];
        pass = (s > 0.5f);
    }
    unsigned m = __ballot_sync(FULLW, pass);
    if (!m) return;
    int lane = threadIdx.x & 31;
    int leader = __ffs(m) - 1;
    int base = 0;
    if (lane == leader) base = atomicAdd(&g_cnt, __popc(m));
    base = __shfl_sync(FULLW, base, leader);
    if (pass) {
        int slot = base + __popc(m & ((1u << lane) - 1));
        if (slot < NSORT) {
            unsigned sb = __float_as_uint(s);
            g_keys[slot] = ((unsigned long long)(~sb) << 32) | (unsigned)n;
        }
    }
}

// ---------------- K1: rank-by-counting sort + gather (4 threads/key) ------
// keys unique (idx in low bits) => rank is an exact permutation.
// key = (~score_bits)<<32 | idx : ascending == descending score, stable ties.
extern "C" __global__ void __launch_bounds__(256)
k1_rank_kernel(const float* __restrict__ x)
{
    __shared__ unsigned long long tile[256];
    __shared__ int srank[64][4];
    const int M = min(g_cnt, NSORT);
    if ((int)(blockIdx.x * 64) >= M) return;          // uniform block early-exit

    const int tid   = threadIdx.x;
    const int key_l = tid & 63;
    const int sub   = tid >> 6;
    const int kslot = blockIdx.x * 64 + key_l;
    const unsigned long long mykey = (kslot < M) ? g_keys[kslot] : ~0ULL;

    int cnt = 0;
    for (int base = 0; base < M; base += 256) {
        int c = base + tid;
        tile[tid] = (c < M) ? g_keys[c] : ~0ULL;      // sentinel never counts
        __syncthreads();
        const unsigned long long* tp = tile + (sub << 6);   // warp-broadcast reads
#pragma unroll 16
        for (int j = 0; j < 64; j++)
            cnt += (tp[j] < mykey);
        __syncthreads();
    }
    srank[key_l][sub] = cnt;
    __syncthreads();

    if (sub == 0 && kslot < M) {
        int rank = srank[key_l][0] + srank[key_l][1]
                 + srank[key_l][2] + srank[key_l][3];
        int idx = (int)(unsigned)mykey;
        float X1 = x[idx];
        float Y1 = x[N_IN + idx];
        float X2 = x[2 * N_IN + idx];
        float Y2 = x[3 * N_IN + idx];
        g_boxes[rank] = make_float4(X1, Y1, X2, Y2);
        g_score[rank] = __uint_as_float(~(unsigned)(mykey >> 32));
        g_area[rank]  = (X2 - X1) * (Y2 - Y1);
    }
}

// ---------------- K2: sparse edges (64x64 tiles, 4 threads/row) -----------
// Triangle-linear grid (ty <= tx); edge (i,j), i<j, packed (i<<13)|j when
//   IoU > 0.5 <=> 3*inter > area_i + area_j + 1e-9 (denominator always > 0).
#define NCT64   (NSORT / 64)                     // 128
#define K2_GRID (NCT64 * (NCT64 + 1) / 2)        // 8256

extern "C" __global__ void __launch_bounds__(256)
k2_edges_kernel()
{
    // linear -> (ty <= tx) triangle decode
    const int L = blockIdx.x;
    int tx = (int)((sqrtf(8.0f * (float)L + 1.0f) - 1.0f) * 0.5f);
    while ((tx + 1) * (tx + 2) / 2 <= L) tx++;
    while (tx * (tx + 1) / 2 > L) tx--;
    const int ty = L - tx * (tx + 1) / 2;

    const int M = min(g_cnt, NSORT);
    const int nct = (M + 63) >> 6;
    if (ty >= nct || tx >= nct) return;

    __shared__ float4 cb[64];
    __shared__ float  ca[64];
    __shared__ unsigned ebuf[4096];     // worst case: full 64x64 tile
    __shared__ int ec, gbase;
    const int t  = threadIdx.x;
    if (t == 0) ec = 0;
    const int j0 = tx << 6;
    if (t < 64) {
        int jg = j0 + t;
        if (jg < M) { cb[t] = g_boxes[jg]; ca[t] = g_area[jg]; }
        else        { cb[t] = make_float4(0, 0, 0, 0); ca[t] = 1e30f; }
    }
    __syncthreads();

    const int row = t >> 2, sub = t & 3;
    const int i   = (ty << 6) + row;
    if (i < M) {
        const float4 b  = g_boxes[i];
        const float  sA = g_area[i] + 1e-9f;
        const int    c1 = min((sub << 4) + 16, M - j0);
#pragma unroll 4
        for (int c = sub << 4; c < c1; c++) {
            int j = j0 + c;
            if (j > i) {
                float4 q = cb[c];
                float iw = fminf(b.z, q.z) - fmaxf(b.x, q.x);
                float ih = fminf(b.w, q.w) - fmaxf(b.y, q.y);
                float inter = fmaxf(iw, 0.f) * fmaxf(ih, 0.f);
                if (3.0f * inter > sA + ca[c]) {
                    int p = atomicAdd(&ec, 1);
                    ebuf[p] = ((unsigned)i << 13) | (unsigned)j;
                }
            }
        }
    }
    __syncthreads();
    if (t == 0 && ec > 0) gbase = atomicAdd(&g_ecnt, ec);
    __syncthreads();
    for (int p = t; p < ec; p += 256) {
        int gp = gbase + p;
        if (gp < ECAP) g_edges[gp] = ebuf[p];
    }
}

// ---------------- K3: fixed-point with live-edge compaction ---------------
#define K3_SMEM (2 * EBUF * 4)     // 192 KB ping-pong edge buffers

extern "C" __global__ void __launch_bounds__(1024, 1)
k3_fixed_kernel(float* __restrict__ out)
{
    extern __shared__ unsigned se[];                  // [2][EBUF]
    __shared__ unsigned keepb[NB32], supb[NB32], nsup[NB32], unkp[NB32];
    __shared__ int notdone, livecnt;
    const int M   = min(g_cnt, NSORT);
    const int tid = threadIdx.x, lane = tid & 31;
    int E = g_ecnt; if (E > ECAP) E = ECAP;
    const int Eover = (E > EBUF) ? (E - EBUF) : 0;    // stays in global, uncompacted

    unsigned* cur = se;
    unsigned* nxt = se + EBUF;
    int curN = min(E, EBUF);

    for (int e = tid; e < curN; e += 1024) cur[e] = g_edges[e];
    if (tid < NB32) { keepb[tid] = 0u; supb[tid] = 0u; }
    __syncthreads();

    for (int round = 0; round < NSORT; round++) {
        if (tid < NB32) { nsup[tid] = 0u; unkp[tid] = 0u; }
        if (tid == 0) { notdone = 0; livecnt = 0; }
        __syncthreads();

        // classify an edge; returns live (both endpoints unknown)
        auto classify = [&](unsigned ed) -> bool {
            int i = (int)(ed >> 13), j = (int)(ed & 8191u);
            unsigned jset = (keepb[j >> 5] | supb[j >> 5]) >> (j & 31);
            if (jset & 1u) return false;                      // j settled
            if ((keepb[i >> 5] >> (i & 31)) & 1u) {
                atomicOr(&nsup[j >> 5], 1u << (j & 31));      // KEEP pred -> SUP
                return false;
            }
            if ((supb[i >> 5] >> (i & 31)) & 1u) return false; // vacuous edge
            atomicOr(&unkp[j >> 5], 1u << (j & 31));          // UNKNOWN pred
            return true;
        };

        // smem edges: classify + warp-aggregated compaction into nxt
        for (int e0 = 0; e0 < curN; e0 += 1024) {
            int e = e0 + tid;
            bool act = (e < curN);
            unsigned ed = act ? cur[e] : 0u;
            bool live = act && classify(ed);
            unsigned m = __ballot_sync(FULLW, live);
            if (m) {
                int leader = __ffs(m) - 1;
                int base = 0;
                if (lane == leader) base = atomicAdd(&livecnt, __popc(m));
                base = __shfl_sync(FULLW, base, leader);
                if (live) nxt[base + __popc(m & ((1u << lane) - 1))] = ed;
            }
        }
        // overflow edges: classify only (never compacted)
        for (int e = tid; e < Eover; e += 1024) classify(g_edges[EBUF + e]);
        __syncthreads();

        if (tid < NB32) {
            int base = tid << 5;
            unsigned valid = (base + 32 <= M) ? 0xffffffffu
                           : (base >= M ? 0u : ((1u << (M - base)) - 1u));
            unsigned unk = ~(keepb[tid] | supb[tid]) & valid;
            if (unk) {
                unsigned ns = nsup[tid] & unk;
                unsigned nk = unk & ~nsup[tid] & ~unkp[tid];
                supb[tid]  |= ns;
                keepb[tid] |= nk;
                if (unk & ~(ns | nk)) notdone = 1;            // benign race
            }
        }
        __syncthreads();
        if (!notdone) break;
        curN = livecnt;
        unsigned* tmp = cur; cur = nxt; nxt = tmp;
        __syncthreads();     // livecnt read complete before next-round reset
    }

    // fused masked output write (replaces K4)
    for (int r = tid; r < N_IN; r += 1024) {
        if (r < M) {
            float m = (float)((keepb[r >> 5] >> (r & 31)) & 1u);
            float4 b = g_boxes[r];
            out[r * 5 + 0] = b.x * m;
            out[r * 5 + 1] = b.y * m;
            out[r * 5 + 2] = b.z * m;
            out[r * 5 + 3] = b.w * m;
            out[r * 5 + 4] = g_score[r] * m;
        } else {
            out[r * 5 + 0] = 0.f;
            out[r * 5 + 1] = 0.f;
            out[r * 5 + 2] = 0.f;
            out[r * 5 + 3] = 0.f;
            out[r * 5 + 4] = 0.f;
        }
    }

    // restore zero-invariants for next call / graph replay
    if (tid == 0) { g_cnt = 0; g_ecnt = 0; }
}

// ---------------- launcher ----------------
extern "C" void kernel_launch(void* const* d_in, const int* in_sizes, int n_in,
                              void* d_out, int out_size)
{
    (void)in_sizes; (void)n_in; (void)out_size;
    const float* x = (const float*)d_in[0];
    float* out = (float*)d_out;

    static bool init_done = false;
    if (!init_done) {
        cudaFuncSetAttribute(k3_fixed_kernel,
                             cudaFuncAttributeMaxDynamicSharedMemorySize, K3_SMEM);
        init_done = true;
    }

    k0_filter_kernel<<<(N_IN + 255) / 256, 256>>>(x);
    k1_rank_kernel<<<NSORT / 64, 256>>>(x);
    k2_edges_kernel<<<K2_GRID, 256>>>();
    k3_fixed_kernel<<<1, 1024, K3_SMEM>>>(out);
}

// round 16
// speedup vs baseline: 1.2763x; 1.2036x over previous
#include <cuda_runtime.h>

// YOLO postprocess: filter(score>0.5) -> sort desc -> greedy NMS(IoU>0.5) -> masked rows.
// x: (1, 84, 8400) f32 channel-major; out: (8400, 5) f32.
//
//   K0 filter (warp-aggregated compaction)
//   K1 rank-by-counting sort + gather (4 threads/key, smem tiles)
//   K2 sparse suppression edge list (64x64 tiles, 4 threads/row, triangle grid)
//      + predecessor bitmap (seeds K3)
//   K3 exact greedy fixed-point with live-edge ping-pong compaction, seeded
//      with no-predecessor rows = KEEP (provably identical to running round 0)
//   K4 masked output write (reads g_M)
//
// Greedy NMS == unique fixed point of:
//   j SUP  iff exists edge (i,j), i<j, i KEEP
//   j KEEP iff every edge (i,j) has i SUP
// Each round the minimum-index unknown row settles => guaranteed convergence.

#define N_IN   8400
#define NSORT  8192
#define FULLW  0xffffffffu
#define ECAP   (1 << 20)      // edge capacity (4 MB scratch; ~25k expected)
#define EBUF   24576          // edges per ping-pong smem buffer (96 KB each)
#define NB32   256            // 8192 bits / 32

// ---------------- global scratch ----------------
__device__ int      g_cnt;          // zero at rest (reset by K3)
__device__ int      g_ecnt;         // zero at rest (reset by K3)
__device__ int      g_M;            // published by K3 for K4
__device__ unsigned g_predb[NB32];  // zero at rest (reset by K3)
__device__ unsigned long long g_keys[NSORT];
__device__ __align__(16) float4 g_boxes[NSORT];
__device__ float    g_score[NSORT];
__device__ float    g_area[NSORT];
__device__ unsigned g_keepw32[NB32];
__device__ unsigned g_edges[ECAP];

// ---------------- K0: filter + compact (order canonicalized by K1) --------
extern "C" __global__ void __launch_bounds__(256)
k0_filter_kernel(const float* __restrict__ x)
{
    const int n = blockIdx.x * 256 + threadIdx.x;
    bool pass = false;
    float s = 0.f;
    if (n < N_IN) {
        s = x[4 * N_IN + n];
        pass = (s > 0.5f);
    }
    unsigned m = __ballot_sync(FULLW, pass);
    if (!m) return;
    int lane = threadIdx.x & 31;
    int leader = __ffs(m) - 1;
    int base = 0;
    if (lane == leader) base = atomicAdd(&g_cnt, __popc(m));
    base = __shfl_sync(FULLW, base, leader);
    if (pass) {
        int slot = base + __popc(m & ((1u << lane) - 1));
        if (slot < NSORT) {
            unsigned sb = __float_as_uint(s);
            g_keys[slot] = ((unsigned long long)(~sb) << 32) | (unsigned)n;
        }
    }
}

// ---------------- K1: rank-by-counting sort + gather (4 threads/key) ------
// keys unique (idx in low bits) => rank is an exact permutation.
// key = (~score_bits)<<32 | idx : ascending == descending score, stable ties.
extern "C" __global__ void __launch_bounds__(256)
k1_rank_kernel(const float* __restrict__ x)
{
    __shared__ unsigned long long tile[256];
    __shared__ int srank[64][4];
    const int M = min(g_cnt, NSORT);
    if ((int)(blockIdx.x * 64) >= M) return;          // uniform block early-exit

    const int tid   = threadIdx.x;
    const int key_l = tid & 63;
    const int sub   = tid >> 6;
    const int kslot = blockIdx.x * 64 + key_l;
    const unsigned long long mykey = (kslot < M) ? g_keys[kslot] : ~0ULL;

    int cnt = 0;
    for (int base = 0; base < M; base += 256) {
        int c = base + tid;
        tile[tid] = (c < M) ? g_keys[c] : ~0ULL;      // sentinel never counts
        __syncthreads();
        const unsigned long long* tp = tile + (sub << 6);   // warp-broadcast reads
#pragma unroll 16
        for (int j = 0; j < 64; j++)
            cnt += (tp[j] < mykey);
        __syncthreads();
    }
    srank[key_l][sub] = cnt;
    __syncthreads();

    if (sub == 0 && kslot < M) {
        int rank = srank[key_l][0] + srank[key_l][1]
                 + srank[key_l][2] + srank[key_l][3];
        int idx = (int)(unsigned)mykey;
        float X1 = x[idx];
        float Y1 = x[N_IN + idx];
        float X2 = x[2 * N_IN + idx];
        float Y2 = x[3 * N_IN + idx];
        g_boxes[rank] = make_float4(X1, Y1, X2, Y2);
        g_score[rank] = __uint_as_float(~(unsigned)(mykey >> 32));
        g_area[rank]  = (X2 - X1) * (Y2 - Y1);
    }
}

// ---------------- K2: sparse edges (64x64 tiles, 4 threads/row) -----------
// Triangle-linear grid (ty <= tx); edge (i,j), i<j, packed (i<<13)|j when
//   IoU > 0.5 <=> 3*inter > area_i + area_j + 1e-9 (denominator always > 0).
// Flush loop also sets predb bit for every target j (seeds K3).
#define NCT64   (NSORT / 64)                     // 128
#define K2_GRID (NCT64 * (NCT64 + 1) / 2)        // 8256

extern "C" __global__ void __launch_bounds__(256)
k2_edges_kernel()
{
    // linear -> (ty <= tx) triangle decode
    const int L = blockIdx.x;
    int tx = (int)((sqrtf(8.0f * (float)L + 1.0f) - 1.0f) * 0.5f);
    while ((tx + 1) * (tx + 2) / 2 <= L) tx++;
    while (tx * (tx + 1) / 2 > L) tx--;
    const int ty = L - tx * (tx + 1) / 2;

    const int M = min(g_cnt, NSORT);
    const int nct = (M + 63) >> 6;
    if (ty >= nct || tx >= nct) return;

    __shared__ float4 cb[64];
    __shared__ float  ca[64];
    __shared__ unsigned ebuf[4096];     // worst case: full 64x64 tile
    __shared__ int ec, gbase;
    const int t  = threadIdx.x;
    if (t == 0) ec = 0;
    const int j0 = tx << 6;
    if (t < 64) {
        int jg = j0 + t;
        if (jg < M) { cb[t] = g_boxes[jg]; ca[t] = g_area[jg]; }
        else        { cb[t] = make_float4(0, 0, 0, 0); ca[t] = 1e30f; }
    }
    __syncthreads();

    const int row = t >> 2, sub = t & 3;
    const int i   = (ty << 6) + row;
    if (i < M) {
        const float4 b  = g_boxes[i];
        const float  sA = g_area[i] + 1e-9f;
        const int    c1 = min((sub << 4) + 16, M - j0);
#pragma unroll 4
        for (int c = sub << 4; c < c1; c++) {
            int j = j0 + c;
            if (j > i) {
                float4 q = cb[c];
                float iw = fminf(b.z, q.z) - fmaxf(b.x, q.x);
                float ih = fminf(b.w, q.w) - fmaxf(b.y, q.y);
                float inter = fmaxf(iw, 0.f) * fmaxf(ih, 0.f);
                if (3.0f * inter > sA + ca[c]) {
                    int p = atomicAdd(&ec, 1);
                    ebuf[p] = ((unsigned)i << 13) | (unsigned)j;
                }
            }
        }
    }
    __syncthreads();
    if (t == 0 && ec > 0) gbase = atomicAdd(&g_ecnt, ec);
    __syncthreads();
    for (int p = t; p < ec; p += 256) {
        int gp = gbase + p;
        unsigned ed = ebuf[p];
        if (gp < ECAP) g_edges[gp] = ed;
        int j = (int)(ed & 8191u);
        atomicOr(&g_predb[j >> 5], 1u << (j & 31));   // j has a predecessor
    }
}

// ---------------- K3: seeded fixed-point with live-edge compaction --------
// Seed: rows with no predecessor are KEEP. This is bit-identical to the
// state after round 0 of the unseeded iteration (round 0 marks unkp[j] for
// every edge target and keeps exactly the no-pred rows), so the fixed point
// is unchanged — round 0's full-E scan + compaction is simply skipped.
#define K3_SMEM (2 * EBUF * 4)     // 192 KB ping-pong edge buffers

extern "C" __global__ void __launch_bounds__(1024, 1)
k3_fixed_kernel()
{
    extern __shared__ unsigned se[];                  // [2][EBUF]
    __shared__ unsigned keepb[NB32], supb[NB32], nsup[NB32], unkp[NB32];
    __shared__ int notdone, livecnt;
    const int M   = min(g_cnt, NSORT);
    const int tid = threadIdx.x, lane = tid & 31;
    int E = g_ecnt; if (E > ECAP) E = ECAP;
    const int Eover = (E > EBUF) ? (E - EBUF) : 0;    // stays in global, uncompacted

    unsigned* cur = se;
    unsigned* nxt = se + EBUF;
    int curN = min(E, EBUF);

    for (int e = tid; e < curN; e += 1024) cur[e] = g_edges[e];
    if (tid < NB32) {
        int base = tid << 5;
        unsigned valid = (base + 32 <= M) ? 0xffffffffu
                       : (base >= M ? 0u : ((1u << (M - base)) - 1u));
        keepb[tid] = valid & ~g_predb[tid];           // seed: no-pred rows KEEP
        supb[tid]  = 0u;
    }
    __syncthreads();

    for (int round = 0; round < NSORT; round++) {
        if (tid < NB32) { nsup[tid] = 0u; unkp[tid] = 0u; }
        if (tid == 0) { notdone = 0; livecnt = 0; }
        __syncthreads();

        // classify an edge; returns live (both endpoints unknown)
        auto classify = [&](unsigned ed) -> bool {
            int i = (int)(ed >> 13), j = (int)(ed & 8191u);
            unsigned jset = (keepb[j >> 5] | supb[j >> 5]) >> (j & 31);
            if (jset & 1u) return false;                      // j settled
            if ((keepb[i >> 5] >> (i & 31)) & 1u) {
                atomicOr(&nsup[j >> 5], 1u << (j & 31));      // KEEP pred -> SUP
                return false;
            }
            if ((supb[i >> 5] >> (i & 31)) & 1u) return false; // vacuous edge
            atomicOr(&unkp[j >> 5], 1u << (j & 31));          // UNKNOWN pred
            return true;
        };

        // smem edges: classify + warp-aggregated compaction into nxt
        for (int e0 = 0; e0 < curN; e0 += 1024) {
            int e = e0 + tid;
            bool act = (e < curN);
            unsigned ed = act ? cur[e] : 0u;
            bool live = act && classify(ed);
            unsigned m = __ballot_sync(FULLW, live);
            if (m) {
                int leader = __ffs(m) - 1;
                int base = 0;
                if (lane == leader) base = atomicAdd(&livecnt, __popc(m));
                base = __shfl_sync(FULLW, base, leader);
                if (live) nxt[base + __popc(m & ((1u << lane) - 1))] = ed;
            }
        }
        // overflow edges: classify only (never compacted)
        for (int e = tid; e < Eover; e += 1024) classify(g_edges[EBUF + e]);
        __syncthreads();

        if (tid < NB32) {
            int base = tid << 5;
            unsigned valid = (base + 32 <= M) ? 0xffffffffu
                           : (base >= M ? 0u : ((1u << (M - base)) - 1u));
            unsigned unk = ~(keepb[tid] | supb[tid]) & valid;
            if (unk) {
                unsigned ns = nsup[tid] & unk;
                unsigned nk = unk & ~nsup[tid] & ~unkp[tid];
                supb[tid]  |= ns;
                keepb[tid] |= nk;
                if (unk & ~(ns | nk)) notdone = 1;            // benign race
            }
        }
        __syncthreads();
        if (!notdone) break;
        curN = livecnt;
        unsigned* tmp = cur; cur = nxt; nxt = tmp;
        __syncthreads();     // livecnt read complete before next-round reset
    }

    if (tid < NB32) { g_keepw32[tid] = keepb[tid]; g_predb[tid] = 0u; }
    // publish M for K4; restore zero-invariants (replaces memset nodes)
    if (tid == 0) { g_M = M; g_cnt = 0; g_ecnt = 0; }
}

// ---------------- K4: masked output write (reads g_M) ----------------
extern "C" __global__ void __launch_bounds__(256)
k4_out_kernel(float* __restrict__ out)
{
    const int r = blockIdx.x * 256 + threadIdx.x;
    if (r >= N_IN) return;
    const int M = g_M;
    if (r < M) {
        float m = (float)((g_keepw32[r >> 5] >> (r & 31)) & 1u);
        float4 b = g_boxes[r];
        out[r * 5 + 0] = b.x * m;
        out[r * 5 + 1] = b.y * m;
        out[r * 5 + 2] = b.z * m;
        out[r * 5 + 3] = b.w * m;
        out[r * 5 + 4] = g_score[r] * m;
    } else {
        out[r * 5 + 0] = 0.f;
        out[r * 5 + 1] = 0.f;
        out[r * 5 + 2] = 0.f;
        out[r * 5 + 3] = 0.f;
        out[r * 5 + 4] = 0.f;
    }
}

// ---------------- launcher ----------------
extern "C" void kernel_launch(void* const* d_in, const int* in_sizes, int n_in,
                              void* d_out, int out_size)
{
    (void)in_sizes; (void)n_in; (void)out_size;
    const float* x = (const float*)d_in[0];
    float* out = (float*)d_out;

    static bool init_done = false;
    if (!init_done) {
        cudaFuncSetAttribute(k3_fixed_kernel,
                             cudaFuncAttributeMaxDynamicSharedMemorySize, K3_SMEM);
        init_done = true;
    }

    k0_filter_kernel<<<(N_IN + 255) / 256, 256>>>(x);
    k1_rank_kernel<<<NSORT / 64, 256>>>(x);
    k2_edges_kernel<<<K2_GRID, 256>>>();
    k3_fixed_kernel<<<1, 1024, K3_SMEM>>>();
    k4_out_kernel<<<(N_IN + 255) / 256, 256>>>(out);
}